// round 3
// baseline (speedup 1.0000x reference)
#include <cuda_runtime.h>

// Four-step 1024-point inverse FFT, 2 threads per row-FFT (64 threads/row):
//   1024 = 32 x 32.  Each FFT-32 = one cross-thread radix-2 stage (distance
//   16) + an in-register FFT-16 with compile-time twiddles.
//   FFT-1 cross stage: shfl.xor(16) within the warp.
//   FFT-2 cross stage: folded into the smem transpose read (each thread reads
//   both halves of its row and immediately combines).
// Inter-FFT twiddles W1024^{b*k1} come from an 8KB per-CTA smem table built
// once with __sincosf (no serial chains). 16 complex values per thread keeps
// registers ~half of round-2, doubling occupancy to hide DRAM latency.

#define NFFT 1024
#define NT   256
#define ROWS_PER_CTA 4          // 2 warps per row, 8 warps per CTA

__device__ __forceinline__ int brev4(int x) {
    return ((x & 1) << 3) | ((x & 2) << 1) | ((x & 4) >> 1) | ((x & 8) >> 3);
}

__device__ __forceinline__ float2 cmulf(float2 a, float2 b) {
    return make_float2(a.x * b.x - a.y * b.y, a.x * b.y + a.y * b.x);
}

// In-place radix-2 DIF FFT-16, inverse sign (W = e^{+2*pi*i/16}).
// Input natural order, output bit-reversed: v[p] holds X[brev4(p)].
// Fully unrolled: all twiddles fold to literal constants.
__device__ __forceinline__ void fft16_dif(float2* v) {
    const float C16[8] = { 1.0f,  0.92387953251f,  0.70710678119f,  0.38268343236f,
                           0.0f, -0.38268343236f, -0.70710678119f, -0.92387953251f };
    const float S16[8] = { 0.0f,  0.38268343236f,  0.70710678119f,  0.92387953251f,
                           1.0f,  0.92387953251f,  0.70710678119f,  0.38268343236f };
    #pragma unroll
    for (int s = 0; s < 4; s++) {
        const int L = 16 >> s, half = L >> 1;
        #pragma unroll
        for (int s0 = 0; s0 < 16; s0 += L) {
            #pragma unroll
            for (int j = 0; j < half; j++) {
                const int i0 = s0 + j, i1 = i0 + half;
                const int tw = j << s;                     // < 8
                const float2 u = v[i0], w = v[i1];
                v[i0] = make_float2(u.x + w.x, u.y + w.y);
                const float dx = u.x - w.x, dy = u.y - w.y;
                v[i1] = make_float2(dx * C16[tw] - dy * S16[tw],
                                    dx * S16[tw] + dy * C16[tw]);
            }
        }
    }
}

__global__ void __launch_bounds__(NT, 4)
ifft1024_v3(const float* __restrict__ re,
            const float* __restrict__ im,
            float* __restrict__ out,
            int batch)
{
    // W1024^{k1*b} table (same for every row) + per-row transpose buffers.
    __shared__ float2 twtab[1024];
    __shared__ float2 tbuf[ROWS_PER_CTA][32 * 33];   // pitch 33 float2: CF both ways

    // W32^m = e^{+2*pi*i*m/32}, m = 0..15 (cross-stage twiddles, compile-time idx)
    const float C32[16] = {
        1.0f,           0.98078528040f,  0.92387953251f,  0.83146961230f,
        0.70710678119f, 0.55557023302f,  0.38268343236f,  0.19509032202f,
        0.0f,          -0.19509032202f, -0.38268343236f, -0.55557023302f,
       -0.70710678119f,-0.83146961230f, -0.92387953251f, -0.98078528040f };
    const float S32[16] = {
        0.0f,           0.19509032202f,  0.38268343236f,  0.55557023302f,
        0.70710678119f, 0.83146961230f,  0.92387953251f,  0.98078528040f,
        1.0f,           0.98078528040f,  0.92387953251f,  0.83146961230f,
        0.70710678119f, 0.55557023302f,  0.38268343236f,  0.19509032202f };

    const int tid  = threadIdx.x;
    const int lane = tid & 31;
    const int warp = tid >> 5;
    const int rowc = warp >> 1;          // row within CTA (0..3)
    const int wq   = warp & 1;           // which warp of the row pair
    const int half = lane >> 4;          // t for FFT-1 / s for FFT-2
    const int b    = 16 * wq + (lane & 15);   // column (FFT-1) / k1-row (FFT-2)

    const size_t row = (size_t)blockIdx.x * ROWS_PER_CTA + rowc;
    const float* __restrict__ rr = re + row * NFFT;
    const float* __restrict__ ri = im + row * NFFT;

    // Load x[32a + b], a = 16*half + m. Each warp instr = two 64B segments.
    float2 v[16];
    #pragma unroll
    for (int m = 0; m < 16; m++) {
        const int n = 512 * half + 32 * m + b;
        v[m].x = rr[n];
        v[m].y = ri[n];
    }

    // Build twiddle table: 4 entries per thread (2*pi/1024 = 6.1359231515e-3).
    #pragma unroll
    for (int e = 0; e < 4; e++) {
        const int idx = tid + NT * e;
        const int k1 = idx >> 5, bb = idx & 31;
        float sn, cs;
        __sincosf(6.135923151542565e-3f * (float)(k1 * bb), &sn, &cs);
        twtab[idx] = make_float2(cs, sn);
    }
    __syncthreads();

    // FFT-1 cross stage (distance 16) via shfl.xor(16):
    //   half=0 keeps x[m]+x[m+16]; half=1 keeps (x[m]-x[m+16])*W32^m.
    #pragma unroll
    for (int m = 0; m < 16; m++) {
        const float ox = __shfl_xor_sync(0xffffffffu, v[m].x, 16);
        const float oy = __shfl_xor_sync(0xffffffffu, v[m].y, 16);
        if (half == 0) {
            v[m].x += ox;
            v[m].y += oy;
        } else {
            const float dx = ox - v[m].x, dy = oy - v[m].y;  // lower - upper
            v[m] = make_float2(dx * C32[m] - dy * S32[m],
                               dx * S32[m] + dy * C32[m]);
        }
    }
    fft16_dif(v);
    // v[p] = A[k1, b], k1 = 2*brev4(p) + half.

    // Twiddle by W1024^{b*k1} and write transpose (consecutive float2s: CF).
    float2* sb = tbuf[rowc];
    #pragma unroll
    for (int p = 0; p < 16; p++) {
        const int k1 = 2 * brev4(p) + half;
        const float2 w = twtab[(k1 << 5) + b];
        sb[k1 * 33 + b] = cmulf(v[p], w);
    }
    __syncthreads();

    // FFT-2: this thread handles k1-row = b, half = s. The distance-16 stage
    // is folded into the read: fetch both halves, combine immediately.
    float2 u[16];
    #pragma unroll
    for (int j = 0; j < 16; j++) {
        const float2 lo = sb[b * 33 + j];
        const float2 hi = sb[b * 33 + 16 + j];
        if (half == 0) {
            u[j] = make_float2(lo.x + hi.x, lo.y + hi.y);
        } else {
            const float dx = lo.x - hi.x, dy = lo.y - hi.y;
            u[j] = make_float2(dx * C32[j] - dy * S32[j],
                               dx * S32[j] + dy * C32[j]);
        }
    }
    fft16_dif(u);
    // u[p] = X[b + 32*k2], k2 = 2*brev4(p) + half.

    // Scaled coalesced stores (two 64B segments per warp instr).
    const float sc = 1.0f / 1024.0f;
    float* __restrict__ outr = out + row * NFFT;
    float* __restrict__ outi = out + (size_t)batch * NFFT + row * NFFT;
    #pragma unroll
    for (int p = 0; p < 16; p++) {
        const int k = b + 32 * (2 * brev4(p) + half);
        outr[k] = u[p].x * sc;
        outi[k] = u[p].y * sc;
    }
}

extern "C" void kernel_launch(void* const* d_in, const int* in_sizes, int n_in,
                              void* d_out, int out_size)
{
    // metadata order: re, im, wr_u, wr_l, wi_u, wi_l (matrices unused: the
    // u/l split sums exactly to the IDFT matrix; the reference pipeline is a
    // normalized 1024-point inverse DFT, computed here directly).
    const float* re = (const float*)d_in[0];
    const float* im = (const float*)d_in[1];
    float* out = (float*)d_out;

    const int batch = in_sizes[0] / NFFT;     // 32768
    ifft1024_v3<<<batch / ROWS_PER_CTA, NT>>>(re, im, out, batch);
}

// round 4
// speedup vs baseline: 1.1583x; 1.1583x over previous
#include <cuda_runtime.h>

// Four-step 1024-point inverse FFT (reference == normalized inverse DFT):
//   1024 = 32 x 32, one warp lane per column, one warp per row.
//   A[k1,b]   = FFT32_a( x[32a+b] )            (register FFT, thread = b = lane)
//   A'[k1,b]  = A[k1,b] * (1/1024) * W1024^{b*k1}
//   X[k1+32k2] = FFT32_b( A'[k1,b] )           (after padded 32x32 smem transpose)
// v4 vs v2: fast __sincosf twiddle bases computed during LDG latency, 4-way
// parallel twiddle generation (chain depth 8 instead of 31), scale folded into
// the twiddles. Same minimal smem traffic (one transpose, re then im).

#define NFFT 1024
#define WARPS_PER_CTA 8
#define NT (32 * WARPS_PER_CTA)

__device__ __forceinline__ int brev5(int x) {
    return ((x & 1) << 4) | ((x & 2) << 2) | (x & 4) | ((x & 8) >> 2) | ((x & 16) >> 4);
}

__device__ __forceinline__ float2 cmulf(float2 a, float2 b) {
    return make_float2(a.x * b.x - a.y * b.y, a.x * b.y + a.y * b.x);
}

// In-place radix-2 DIF FFT-32, inverse sign (W = e^{+2*pi*i/32}).
// Input natural order; output bit-reversed: x[p] holds X[brev5(p)].
// Fully unrolled: all twiddles become literal constants.
__device__ __forceinline__ void fft32_dif(float* xr, float* xi) {
    const float TC[16] = {
        1.0f,           0.98078528040f,  0.92387953251f,  0.83146961230f,
        0.70710678119f, 0.55557023302f,  0.38268343236f,  0.19509032202f,
        0.0f,          -0.19509032202f, -0.38268343236f, -0.55557023302f,
       -0.70710678119f,-0.83146961230f, -0.92387953251f, -0.98078528040f };
    const float TS[16] = {
        0.0f,           0.19509032202f,  0.38268343236f,  0.55557023302f,
        0.70710678119f, 0.83146961230f,  0.92387953251f,  0.98078528040f,
        1.0f,           0.98078528040f,  0.92387953251f,  0.83146961230f,
        0.70710678119f, 0.55557023302f,  0.38268343236f,  0.19509032202f };

    #pragma unroll
    for (int s = 0; s < 5; s++) {
        const int L = 32 >> s;
        const int half = L >> 1;
        #pragma unroll
        for (int s0 = 0; s0 < 32; s0 += L) {
            #pragma unroll
            for (int j = 0; j < half; j++) {
                const int i0 = s0 + j;
                const int i1 = i0 + half;
                const int tw = j << s;              // < 16
                const float ur = xr[i0], ui = xi[i0];
                const float vr = xr[i1], vi = xi[i1];
                const float dr = ur - vr, di = ui - vi;
                xr[i0] = ur + vr;
                xi[i0] = ui + vi;
                xr[i1] = dr * TC[tw] - di * TS[tw];
                xi[i1] = dr * TS[tw] + di * TC[tw];
            }
        }
    }
}

__global__ void __launch_bounds__(NT, 3)
ifft1024_v4(const float* __restrict__ re,
            const float* __restrict__ im,
            float* __restrict__ out,
            int batch)
{
    __shared__ float tbuf[WARPS_PER_CTA][32 * 33];   // pitch 33: CF both directions

    const int lane = threadIdx.x & 31;
    const int w    = threadIdx.x >> 5;
    const size_t row = (size_t)blockIdx.x * WARPS_PER_CTA + w;

    const float* __restrict__ rr = re + row * NFFT;
    const float* __restrict__ ri = im + row * NFFT;

    // Load x[32a + lane] (each warp instruction = one coalesced 128B segment).
    float xr[32], xi[32];
    #pragma unroll
    for (int a = 0; a < 32; a++) {
        xr[a] = rr[32 * a + lane];
        xi[a] = ri[32 * a + lane];
    }

    // Twiddle bases (data-independent: overlaps the LDG latency).
    // w1 = W1024^b = e^{+i*2*pi*b/1024}, b = lane (arg <= 0.19 rad: fast path).
    float2 w1;
    __sincosf(6.135923151542565e-3f * (float)lane, &w1.y, &w1.x);
    const float2 w2  = cmulf(w1, w1);
    const float2 w4  = cmulf(w2, w2);
    const float2 w8  = cmulf(w4, w4);     // W^{8b}
    const float2 w16 = cmulf(w8, w8);     // W^{16b}
    const float2 w24 = cmulf(w16, w8);    // W^{24b}

    // FFT over a.  xr[p] = A[brev5(p), lane].
    fft32_dif(xr, xi);

    // Apply s*W1024^{b*k1} for all k1 (scale folded in; applied pre-FFT-2,
    // which commutes). 4-way generation: chain depth 8 instead of 31.
    {
        float2 ch = make_float2(1.0f / 1024.0f, 0.0f);   // s * W^{l*b}, l = 0
        #pragma unroll
        for (int l = 0; l < 8; l++) {
            const float2 t0 = ch;
            const float2 t1 = cmulf(ch, w8);
            const float2 t2 = cmulf(ch, w16);
            const float2 t3 = cmulf(ch, w24);
            const int p0 = brev5(l);
            const int p1 = brev5(l + 8);
            const int p2 = brev5(l + 16);
            const int p3 = brev5(l + 24);
            float ar, ai;
            ar = xr[p0]; ai = xi[p0];
            xr[p0] = ar * t0.x - ai * t0.y;  xi[p0] = ar * t0.y + ai * t0.x;
            ar = xr[p1]; ai = xi[p1];
            xr[p1] = ar * t1.x - ai * t1.y;  xi[p1] = ar * t1.y + ai * t1.x;
            ar = xr[p2]; ai = xi[p2];
            xr[p2] = ar * t2.x - ai * t2.y;  xi[p2] = ar * t2.y + ai * t2.x;
            ar = xr[p3]; ai = xi[p3];
            xr[p3] = ar * t3.x - ai * t3.y;  xi[p3] = ar * t3.y + ai * t3.x;
            ch = cmulf(ch, w1);
        }
    }

    // 32x32 transpose through padded smem, re then im (buffer reused).
    float* sb = tbuf[w];
    #pragma unroll
    for (int k1 = 0; k1 < 32; k1++) sb[k1 * 33 + lane] = xr[brev5(k1)];
    __syncwarp();
    #pragma unroll
    for (int b = 0; b < 32; b++) xr[b] = sb[lane * 33 + b];
    __syncwarp();
    #pragma unroll
    for (int k1 = 0; k1 < 32; k1++) sb[k1 * 33 + lane] = xi[brev5(k1)];
    __syncwarp();
    #pragma unroll
    for (int b = 0; b < 32; b++) xi[b] = sb[lane * 33 + b];

    // FFT over b.  xr[p] = X[lane + 32*brev5(p)]  (already scaled).
    fft32_dif(xr, xi);

    // Coalesced stores (128B per warp instruction).
    float* __restrict__ outr = out + row * NFFT;
    float* __restrict__ outi = out + (size_t)batch * NFFT + row * NFFT;
    #pragma unroll
    for (int p = 0; p < 32; p++) {
        const int k2 = brev5(p);
        outr[lane + 32 * k2] = xr[p];
        outi[lane + 32 * k2] = xi[p];
    }
}

extern "C" void kernel_launch(void* const* d_in, const int* in_sizes, int n_in,
                              void* d_out, int out_size)
{
    // metadata order: re, im, wr_u, wr_l, wi_u, wi_l (matrices unused: the
    // u/l split sums exactly to the IDFT matrix; the reference pipeline is a
    // normalized 1024-point inverse DFT, computed here directly).
    const float* re = (const float*)d_in[0];
    const float* im = (const float*)d_in[1];
    float* out = (float*)d_out;

    const int batch = in_sizes[0] / NFFT;            // 32768
    ifft1024_v4<<<batch / WARPS_PER_CTA, NT>>>(re, im, out, batch);
}